// round 14
// baseline (speedup 1.0000x reference)
#include <cuda_runtime.h>
#include <cuda_fp16.h>
#include <math.h>

// ---------------------------------------------------------------------------
// DCRNN 2-layer DCGRU. B=16, N=512, HID=64, K=2, T_in=12, T_out=12.
// Pure fp16 tensor-core GEMMs (fp32 accum). G4 = [Wf; Wb; Wf^2; Wb^2].
// R14: the layer-0 scalar input di is DECOUPLED from the hop chains:
// chains hop h only (all C = 1024/2048), and layer-0 gates add the di
// contribution analytically (di cached in smem; per-CTA skinny fp32 GEMV
// U_s = G_s·di, then += Σ_s U_s·w_s). This removes the di dependency from
// A1, so the decoder pipelines like the encoder (7 serial launches/step).
// ---------------------------------------------------------------------------

#define NN   512
#define BB   16
#define HID  64
#define NB   (NN*BB)          // 8192
#define F1   128
#define C1   (BB*F1)          // 2048
#define CH   (BB*HID)         // 1024
#define TIN  12
#define TOUT 12

#define KC   32
#define APP  40
#define BPP  72
#define GAP  24
#define GBP  72

#define KP0  (5*HID)          // 320 (layer0 gate K, h-part only)
#define KP1  (5*F1)           // 640

typedef __half f16;

// ---------------- device scratch -------------------------------------------
__device__ float g_G [4*NN*NN];
__device__ f16   g_Gh[4*NN*NN];
__device__ float g_cs[NN];
__device__ float g_h0[NB*HID];
__device__ float g_h1[NB*HID];
__device__ f16   g_SA [NN*CH];       // h0 (fp16), row n, col b*64+f
__device__ f16   g_SB [2*NN*C1];     // step-parity double buffer [h0|h1]
__device__ f16   g_S12a[4*NN*CH];
__device__ f16   g_S12b[4*NN*C1];
__device__ f16   g_T0a [NN*CH];
__device__ f16   g_T12a[4*NN*CH];
__device__ f16   g_T0b [NN*CH];
__device__ f16   g_T12b[4*NN*CH];
__device__ float g_r0[NB*HID];
__device__ float g_z0[NB*HID];
__device__ float g_r1[NB*HID];
__device__ float g_z1[NB*HID];
__device__ f16   g_diAll[TIN*NB];    // encoder di columns (fp16, node*16+b)
__device__ f16   g_dih[NB];          // decoder di (written by B4 proj)
#define OW0R 0
#define OW0Z (KP0*HID)
#define OW0N (2*KP0*HID)
#define OW1R (3*KP0*HID)
#define OW1Z (3*KP0*HID + KP1*HID)
#define OW1N (3*KP0*HID + 2*KP1*HID)
#define WTOT (3*KP0*HID + 3*KP1*HID)
__device__ f16   g_Wsh[WTOT];
__device__ float g_Wdi[3*5*HID];     // di-feature weight rows: [r|z|n][5][64]

// ---------------- PTX helpers ----------------------------------------------
__device__ __forceinline__ void cp16(void* dst, const void* src) {
    unsigned d = (unsigned)__cvta_generic_to_shared(dst);
    asm volatile("cp.async.ca.shared.global [%0], [%1], 16;\n" :: "r"(d), "l"(src));
}
#define CP_COMMIT() asm volatile("cp.async.commit_group;\n")
#define CP_WAIT(n)  asm volatile("cp.async.wait_group %0;\n" :: "n"(n))

__device__ __forceinline__ void ldsm4(unsigned* r, const void* p) {
    unsigned a = (unsigned)__cvta_generic_to_shared(p);
    asm volatile("ldmatrix.sync.aligned.m8n8.x4.shared.b16 {%0,%1,%2,%3}, [%4];"
                 : "=r"(r[0]), "=r"(r[1]), "=r"(r[2]), "=r"(r[3]) : "r"(a));
}
__device__ __forceinline__ void ldsm4t(unsigned* r, const void* p) {
    unsigned a = (unsigned)__cvta_generic_to_shared(p);
    asm volatile("ldmatrix.sync.aligned.m8n8.x4.trans.shared.b16 {%0,%1,%2,%3}, [%4];"
                 : "=r"(r[0]), "=r"(r[1]), "=r"(r[2]), "=r"(r[3]) : "r"(a));
}
#define MMA_F16(d, a, b0v, b1v)                                               \
    asm("mma.sync.aligned.m16n8k16.row.col.f32.f16.f16.f32 "                  \
        "{%0,%1,%2,%3}, {%4,%5,%6,%7}, {%8,%9}, {%0,%1,%2,%3};"               \
        : "+f"(d[0]), "+f"(d[1]), "+f"(d[2]), "+f"(d[3])                      \
        : "r"(a[0]), "r"(a[1]), "r"(a[2]), "r"(a[3]), "r"(b0v), "r"(b1v))

__device__ __forceinline__ void store2(f16* Y, size_t off, float vx, float vy) {
    __half2 hh;
    hh.x = __float2half_rn(vx);
    hh.y = __float2half_rn(vy);
    *reinterpret_cast<__half2*>(&Y[off]) = hh;
}
__device__ __forceinline__ void emit1(float v, f16* X, size_t idx) {
    X[idx] = __float2half_rn(v);
}

// ---------------- setup kernels --------------------------------------------
__global__ void rownorm_k(const float* __restrict__ A, float* __restrict__ G) {
    int i = blockIdx.x;
    __shared__ float red[256];
    float s = 0.f;
    for (int j = threadIdx.x; j < NN; j += 256) s += A[i*NN + j];
    red[threadIdx.x] = s; __syncthreads();
    for (int off = 128; off; off >>= 1) {
        if (threadIdx.x < off) red[threadIdx.x] += red[threadIdx.x + off];
        __syncthreads();
    }
    float d = red[0] + 1e-6f;
    for (int j = threadIdx.x; j < NN; j += 256) G[i*NN + j] = A[i*NN + j] / d;
}
__global__ void colsum_k(const float* __restrict__ A, float* __restrict__ cs) {
    int c = blockIdx.x * blockDim.x + threadIdx.x;
    if (c < NN) {
        float s = 0.f;
        for (int r = 0; r < NN; r++) s += A[r*NN + c];
        cs[c] = s;
    }
}
__global__ void fill_wb_k(const float* __restrict__ A, const float* __restrict__ cs,
                          float* __restrict__ G) {
    int i = blockIdx.x;
    float d = cs[i] + 1e-6f;
    for (int j = threadIdx.x; j < NN; j += 256) G[(NN+i)*NN + j] = A[j*NN + i] / d;
}
__global__ void square_k(const float* __restrict__ G, float* __restrict__ Out) {
    const float* Am = G + (size_t)blockIdx.z*NN*NN;
    float* Cm = Out + (size_t)(2 + blockIdx.z)*NN*NN;
    const int m0 = blockIdx.y * 64, n0 = blockIdx.x * 64;
    const int tid = threadIdx.x;
    const int tx = tid & 15, ty = tid >> 4;
    __shared__ float As[16][64];
    __shared__ float Bs[16][64];
    float acc[4][4];
    #pragma unroll
    for (int i = 0; i < 4; i++)
        #pragma unroll
        for (int j = 0; j < 4; j++) acc[i][j] = 0.f;
    for (int k0 = 0; k0 < NN; k0 += 16) {
        {
            int m = tid >> 2, k4 = (tid & 3) * 4;
            float4 w = *reinterpret_cast<const float4*>(&Am[(size_t)(m0+m)*NN + k0 + k4]);
            As[k4+0][m] = w.x; As[k4+1][m] = w.y; As[k4+2][m] = w.z; As[k4+3][m] = w.w;
        }
        {
            int k = tid >> 4, c4 = (tid & 15) * 4;
            float4 v = *reinterpret_cast<const float4*>(&Am[(size_t)(k0+k)*NN + n0 + c4]);
            *reinterpret_cast<float4*>(&Bs[k][c4]) = v;
        }
        __syncthreads();
        #pragma unroll
        for (int k = 0; k < 16; k++) {
            float a[4], b[4];
            #pragma unroll
            for (int i = 0; i < 4; i++) a[i] = As[k][ty + 16*i];
            #pragma unroll
            for (int j = 0; j < 4; j++) b[j] = Bs[k][tx + 16*j];
            #pragma unroll
            for (int i = 0; i < 4; i++)
                #pragma unroll
                for (int j = 0; j < 4; j++) acc[i][j] += a[i] * b[j];
        }
        __syncthreads();
    }
    #pragma unroll
    for (int i = 0; i < 4; i++)
        #pragma unroll
        for (int j = 0; j < 4; j++)
            Cm[(size_t)(m0 + ty + 16*i)*NN + n0 + tx + 16*j] = acc[i][j];
}
__global__ void cvt_G_k(const float* __restrict__ G, f16* __restrict__ Gh) {
    int i = blockIdx.x * blockDim.x + threadIdx.x;
    if (i < 4*NN*NN) Gh[i] = __float2half_rn(G[i]);
}
// layer0 weights: take only the h-feature rows (skip the di row per slice)
__global__ void cvt_W0_k(const float* __restrict__ W, f16* __restrict__ Wh) {
    int i = blockIdx.x * blockDim.x + threadIdx.x;
    if (i >= KP0*HID) return;
    int row = i >> 6, c = i & 63;
    int s = row >> 6, f = row & 63;
    Wh[i] = __float2half_rn(W[(size_t)(s*65 + 1 + f)*HID + c]);
}
// di-feature weight rows (fp32): out[s*64+c] = W[(s*65)*64 + c]
__global__ void cvt_Wdi_k(const float* __restrict__ W, float* __restrict__ out) {
    int i = blockIdx.x * blockDim.x + threadIdx.x;
    if (i < 5*HID) {
        int s = i >> 6, c = i & 63;
        out[i] = W[(size_t)(s*65)*HID + c];
    }
}
__global__ void cvt_W1_k(const float* __restrict__ W, f16* __restrict__ Wh) {
    int i = blockIdx.x * blockDim.x + threadIdx.x;
    if (i < KP1*HID) Wh[i] = __float2half_rn(W[i]);
}
__global__ void prep_di_k(const float* __restrict__ x, f16* __restrict__ diAll) {
    int i = blockIdx.x * blockDim.x + threadIdx.x;
    if (i >= TIN*NB) return;
    int t = i / NB, r = i - t*NB;
    int node = r >> 4, b = r & 15;
    diAll[i] = __float2half_rn(x[b*(TIN*NN) + t*NN + node]);
}
__global__ void zero2_k(float* a, float* b, int n) {
    int i = blockIdx.x * blockDim.x + threadIdx.x;
    if (i < n) { a[i] = 0.f; b[i] = 0.f; }
}
__global__ void zero_h_k(f16* a, int n) {
    int i = blockIdx.x * blockDim.x + threadIdx.x;
    if (i < n) a[i] = __float2half_rn(0.f);
}

// ---------------- stacked hop GEMM, dual-job, pure fp16 --------------------
struct HopJob {
    const f16* X;
    f16* Y;
    int C, nt;
};

__global__ __launch_bounds__(256, 4)
void hop4_mma(HopJob j0, HopJob j1)
{
    const int tile = blockIdx.x;
    HopJob J; int lt;
    if (tile < j0.nt) { J = j0; lt = tile; }
    else              { J = j1; lt = tile - j0.nt; }
    const int m0 = (lt & 15) << 7;
    const int c0 = (lt >> 4) << 6;
    const int C = J.C;

    __shared__ f16 Ash[2][128][APP];
    __shared__ f16 Bsh[2][KC][BPP];

    const int tid = threadIdx.x;
    const int wid = tid >> 5, lane = tid & 31;
    const int wm = (wid >> 1) * 32;
    const int wn = (wid & 1) * 32;
    const int g = lane >> 2, t4 = lane & 3;
    const int ar = tid >> 1, aj = (tid & 1) * 16;
    const int bk = tid >> 3, bj = (tid & 7) * 8;

    float acc[2][4][4];
    #pragma unroll
    for (int mi = 0; mi < 2; mi++)
        #pragma unroll
        for (int ni = 0; ni < 4; ni++)
            #pragma unroll
            for (int q = 0; q < 4; q++) acc[mi][ni][q] = 0.f;

    auto load_A = [&](int buf, int k0) {
        const f16* a1 = g_Gh + (size_t)(m0+ar)*NN + k0 + aj;
        cp16(&Ash[buf][ar][aj],   a1);
        cp16(&Ash[buf][ar][aj+8], a1+8);
    };
    auto load_B = [&](int buf, int k0) {
        cp16(&Bsh[buf][bk][bj], J.X + (size_t)(k0+bk)*C + c0 + bj);
    };

    load_A(0, 0);
#if __CUDA_ARCH__ >= 900
    cudaGridDependencySynchronize();
#endif
    load_B(0, 0);
    CP_COMMIT();

    const int NIT = NN / KC;
    for (int it = 0; it < NIT; it++) {
        int buf = it & 1;
        if (it + 1 < NIT) {
            load_A(buf ^ 1, (it+1)*KC);
            load_B(buf ^ 1, (it+1)*KC);
            CP_COMMIT(); CP_WAIT(1);
        } else {
            CP_WAIT(0);
        }
        __syncthreads();

        #pragma unroll
        for (int kk = 0; kk < KC; kk += 16) {
            const int arow = lane & 15;
            const int acol = kk + ((lane >> 4) << 3);
            unsigned ah[2][4];
            #pragma unroll
            for (int mi = 0; mi < 2; mi++)
                ldsm4(ah[mi], &Ash[buf][wm + mi*16 + arow][acol]);
            const int brow = kk + (lane & 15);
            #pragma unroll
            for (int np = 0; np < 2; np++) {
                const int bcol = wn + np*16 + ((lane >> 4) << 3);
                unsigned bh[4];
                ldsm4t(bh, &Bsh[buf][brow][bcol]);
                #pragma unroll
                for (int h2 = 0; h2 < 2; h2++) {
                    int ni = np*2 + h2;
                    #pragma unroll
                    for (int mi = 0; mi < 2; mi++)
                        MMA_F16(acc[mi][ni], ah[mi], bh[h2*2], bh[h2*2+1]);
                }
            }
        }
        __syncthreads();
    }

    #pragma unroll
    for (int mi = 0; mi < 2; mi++) {
        #pragma unroll
        for (int ni = 0; ni < 4; ni++) {
            int ncol = c0 + wn + ni*8 + t4*2;
            int m1 = m0 + wm + mi*16 + g;
            store2(J.Y, (size_t)m1*C + ncol,     acc[mi][ni][0], acc[mi][ni][1]);
            store2(J.Y, (size_t)(m1+8)*C + ncol, acc[mi][ni][2], acc[mi][ni][3]);
        }
    }
}

// ---------------- gate GEMM, dual-job, fp16 + analytic di term -------------
struct GateArgs {
    const f16 *Ah[5];
    const f16 *Bh[5];
    int strideA, strideB, split, Fp, nt;
    const f16 *W1h; const float* b1; float* Y1;
    const f16 *W2h; const float* b2; float* Y2;
    const float* zg; float* h;
    const float* hmul; f16* t0;
    f16* e1; int e1s, e1o;
    f16* e2; int e2s, e2o;
    const f16* dic;                  // 512x16 di (fp16) or null (layer1)
    const float *Wd1, *Wd2;          // [5][64] di weight rows per gate
    int fuse, t;                     // fuse==2: decoder proj -> out + dO
    const float *Wp, *bp; float* out;
    f16* dO;
    int mode;
};

__global__ __launch_bounds__(128, 4)
void gate_mma(GateArgs a0, GateArgs a1)
{
    const int tile = blockIdx.x;
    const GateArgs& a = (tile < a0.nt) ? a0 : a1;
    const int lt = (tile < a0.nt) ? tile : tile - a0.nt;
    const int zsel = lt >> 7;
    const int m0 = (lt & 127) << 6;

    const f16* Wh = (a.mode == 0 && zsel) ? a.W2h : a.W1h;
    const float* bl = (a.mode == 0 && zsel) ? a.b2 : a.b1;
    float* Yl = (a.mode == 0 && zsel) ? a.Y2 : a.Y1;

    const int tid = threadIdx.x;
    const int wid = tid >> 5, lane = tid & 31;
    const int g = lane >> 2, t4 = lane & 3;
    const int CPS = a.Fp >> 4;

    __shared__ f16 Ash[2][64][GAP];
    __shared__ f16 Bsh[2][16][GBP];
    __shared__ f16 Dis[NB / 4 * 0 + 8192];   // full di matrix (512x16)
    __shared__ float Us[4][4][16];

    float acc[8][4];
    #pragma unroll
    for (int ni = 0; ni < 8; ni++)
        #pragma unroll
        for (int q = 0; q < 4; q++) acc[ni][q] = 0.f;

    const int arw = tid >> 1, ja = (tid & 1) * 8;
    const int bkr = tid >> 3, bjc = (tid & 7) * 8;

    auto load_W = [&](int buf, int kidx) {
        int gk = kidx*16 + bkr;
        cp16(&Bsh[buf][bkr][bjc], Wh + (size_t)gk*HID + bjc);
    };
    auto load_X = [&](int buf, int kidx) {
        int s = kidx / CPS;
        int f0 = (kidx - s*CPS)*16 + ja;
        const f16* sh;
        if (f0 < a.split) sh = a.Ah[s] + (size_t)(m0+arw)*a.strideA + f0;
        else              sh = a.Bh[s] + (size_t)(m0+arw)*a.strideB + (f0 - a.split);
        cp16(&Ash[buf][arw][ja], sh);
    };

    load_W(0, 0);
#if __CUDA_ARCH__ >= 900
    cudaGridDependencySynchronize();
#endif
    if (a.dic) {
        #pragma unroll
        for (int i = 0; i < 8; i++)
            cp16(&Dis[(i*128 + tid)*8], a.dic + (i*128 + tid)*8);
    }
    load_X(0, 0);
    CP_COMMIT();

    const int NIT = 5 * CPS;
    for (int it = 0; it < NIT; it++) {
        int buf = it & 1;
        if (it + 1 < NIT) {
            load_W(buf ^ 1, it+1);
            load_X(buf ^ 1, it+1);
            CP_COMMIT(); CP_WAIT(1);
        } else {
            CP_WAIT(0);
        }
        __syncthreads();

        const int arow = lane & 15;
        const int acol = (lane >> 4) << 3;
        unsigned ah[4];
        ldsm4(ah, &Ash[buf][wid*16 + arow][acol]);
        const int brow = lane & 15;
        #pragma unroll
        for (int np = 0; np < 4; np++) {
            const int bcol = np*16 + ((lane >> 4) << 3);
            unsigned bh[4];
            ldsm4t(bh, &Bsh[buf][brow][bcol]);
            #pragma unroll
            for (int h2 = 0; h2 < 2; h2++) {
                int ni = np*2 + h2;
                MMA_F16(acc[ni], ah, bh[h2*2], bh[h2*2+1]);
            }
        }
        __syncthreads();
    }

    // ---- analytic di contribution: U_s = (G_s . di)[node, b], s=1..4 ----
    if (a.dic) {
        #pragma unroll
        for (int rep = 0; rep < 2; rep++) {
            int o = tid + rep*128;
            int s = o >> 6;
            int nloc = (o >> 4) & 3;
            int b = o & 15;
            int blk = (0x3120 >> (s*4)) & 0xF;     // slice s+1 -> block
            int node = (m0 >> 4) + nloc;
            const __half2* grow2 = reinterpret_cast<const __half2*>(
                g_Gh + ((size_t)(blk*NN + node))*NN);
            float av = 0.f;
            #pragma unroll 8
            for (int k2 = 0; k2 < NN/2; k2++) {
                float2 gv = __half22float2(grow2[k2]);
                av += gv.x * __half2float(Dis[(2*k2)*16 + b]);
                av += gv.y * __half2float(Dis[(2*k2+1)*16 + b]);
            }
            Us[s][nloc][b] = av;
        }
        __syncthreads();
    }

    const bool write_t0 = (a.mode == 0) && (zsel == 0) && (a.t0 != nullptr);
    const float* Wd = (a.mode == 0 && zsel) ? a.Wd2 : a.Wd1;
    float partial[2] = {0.f, 0.f};
    #pragma unroll
    for (int ni = 0; ni < 8; ni++) {
        int c = ni*8 + t4*2;
        float b0 = bl[c], b1v = bl[c+1];
        #pragma unroll
        for (int half = 0; half < 2; half++) {
            int m = m0 + wid*16 + g + half*8;
            float vx = acc[ni][half*2]   + b0;
            float vy = acc[ni][half*2+1] + b1v;
            if (a.dic) {
                int rel = m - m0;
                int nloc = rel >> 4, bb = rel & 15;
                float dval = __half2float(Dis[m & (NB-1)]);
                float u1 = Us[0][nloc][bb], u2 = Us[1][nloc][bb];
                float u3 = Us[2][nloc][bb], u4 = Us[3][nloc][bb];
                vx += dval*Wd[c]   + u1*Wd[64+c]   + u2*Wd[128+c]
                    + u3*Wd[192+c] + u4*Wd[256+c];
                vy += dval*Wd[c+1] + u1*Wd[64+c+1] + u2*Wd[128+c+1]
                    + u3*Wd[192+c+1] + u4*Wd[256+c+1];
            }
            size_t off = (size_t)m*HID + c;
            if (a.mode == 0) {
                float2 o;
                o.x = 1.f / (1.f + expf(-vx));
                o.y = 1.f / (1.f + expf(-vy));
                *reinterpret_cast<float2*>(&Yl[off]) = o;
                if (write_t0) {
                    float2 hh = *reinterpret_cast<const float2*>(&a.hmul[off]);
                    store2(a.t0, off, o.x * hh.x, o.y * hh.y);
                }
            } else {
                float2 zz = *reinterpret_cast<const float2*>(&a.zg[off]);
                float2 hh = *reinterpret_cast<float2*>(&a.h[off]);
                float2 o;
                o.x = (1.f - zz.x) * hh.x + zz.x * tanhf(vx);
                o.y = (1.f - zz.y) * hh.y + zz.y * tanhf(vy);
                *reinterpret_cast<float2*>(&a.h[off]) = o;
                if (a.e1) store2(a.e1, (size_t)m*a.e1s + a.e1o + c, o.x, o.y);
                if (a.e2) store2(a.e2, (size_t)m*a.e2s + a.e2o + c, o.x, o.y);
                if (a.fuse == 2) partial[half] += o.x * a.Wp[c] + o.y * a.Wp[c+1];
            }
        }
    }

    if (a.mode == 1 && a.fuse == 2) {
        #pragma unroll
        for (int half = 0; half < 2; half++) {
            float p = partial[half];
            p += __shfl_xor_sync(0xffffffffu, p, 1);
            p += __shfl_xor_sync(0xffffffffu, p, 2);
            int m = m0 + wid*16 + g + half*8;
            if (t4 == 0) {
                int node = m >> 4, b = m & 15;
                float s = p + a.bp[0];
                a.out[b*(TOUT*NN) + a.t*NN + node] = s;
                emit1(s, a.dO, (size_t)m);
            }
        }
    }
}

// ---------------- host driver ----------------------------------------------
extern "C" void kernel_launch(void* const* d_in, const int* in_sizes, int n_in,
                              void* d_out, int out_size)
{
    const float* x   = (const float*)d_in[0];
    const float* A   = (const float*)d_in[1];
    const float* Wr0 = (const float*)d_in[2];
    const float* br0 = (const float*)d_in[3];
    const float* Wz0 = (const float*)d_in[4];
    const float* bz0 = (const float*)d_in[5];
    const float* Wn0 = (const float*)d_in[6];
    const float* bn0 = (const float*)d_in[7];
    const float* Wr1 = (const float*)d_in[8];
    const float* br1 = (const float*)d_in[9];
    const float* Wz1 = (const float*)d_in[10];
    const float* bz1 = (const float*)d_in[11];
    const float* Wn1 = (const float*)d_in[12];
    const float* bn1 = (const float*)d_in[13];
    const float* Wp  = (const float*)d_in[14];
    const float* bp  = (const float*)d_in[15];
    float* out = (float*)d_out;

    float *G, *cs, *h0, *h1, *r0, *z0, *r1, *z1, *Wdi;
    f16 *Gh, *SA, *SB, *S12a, *S12b, *T0a, *T12a, *T0b, *T12b, *Wsh, *diAll, *dih;
    cudaGetSymbolAddress((void**)&G,     g_G);
    cudaGetSymbolAddress((void**)&Gh,    g_Gh);
    cudaGetSymbolAddress((void**)&cs,    g_cs);
    cudaGetSymbolAddress((void**)&h0,    g_h0);
    cudaGetSymbolAddress((void**)&h1,    g_h1);
    cudaGetSymbolAddress((void**)&SA,    g_SA);
    cudaGetSymbolAddress((void**)&SB,    g_SB);
    cudaGetSymbolAddress((void**)&S12a,  g_S12a);
    cudaGetSymbolAddress((void**)&S12b,  g_S12b);
    cudaGetSymbolAddress((void**)&T0a,   g_T0a);
    cudaGetSymbolAddress((void**)&T12a,  g_T12a);
    cudaGetSymbolAddress((void**)&T0b,   g_T0b);
    cudaGetSymbolAddress((void**)&T12b,  g_T12b);
    cudaGetSymbolAddress((void**)&r0,    g_r0);
    cudaGetSymbolAddress((void**)&z0,    g_z0);
    cudaGetSymbolAddress((void**)&r1,    g_r1);
    cudaGetSymbolAddress((void**)&z1,    g_z1);
    cudaGetSymbolAddress((void**)&Wsh,   g_Wsh);
    cudaGetSymbolAddress((void**)&Wdi,   g_Wdi);
    cudaGetSymbolAddress((void**)&diAll, g_diAll);
    cudaGetSymbolAddress((void**)&dih,   g_dih);

    rownorm_k<<<NN, 256>>>(A, G);
    colsum_k<<<2, 256>>>(A, cs);
    fill_wb_k<<<NN, 256>>>(A, cs, G);
    square_k<<<dim3(8, 8, 2), 256>>>(G, G);
    cvt_G_k<<<(4*NN*NN + 255)/256, 256>>>(G, Gh);
    int g0 = (KP0*HID + 255)/256, g1 = (KP1*HID + 255)/256;
    cvt_W0_k<<<g0, 256>>>(Wr0, Wsh + OW0R);
    cvt_W0_k<<<g0, 256>>>(Wz0, Wsh + OW0Z);
    cvt_W0_k<<<g0, 256>>>(Wn0, Wsh + OW0N);
    cvt_W1_k<<<g1, 256>>>(Wr1, Wsh + OW1R);
    cvt_W1_k<<<g1, 256>>>(Wz1, Wsh + OW1Z);
    cvt_W1_k<<<g1, 256>>>(Wn1, Wsh + OW1N);
    cvt_Wdi_k<<<2, 256>>>(Wr0, Wdi + 0*5*HID);
    cvt_Wdi_k<<<2, 256>>>(Wz0, Wdi + 1*5*HID);
    cvt_Wdi_k<<<2, 256>>>(Wn0, Wdi + 2*5*HID);
    prep_di_k<<<(TIN*NB + 255)/256, 256>>>(x, diAll);
    zero2_k<<<(NB*HID + 255)/256, 256>>>(h0, h1, NB*HID);
    zero_h_k<<<(NN*CH + 255)/256, 256>>>(SA, NN*CH);
    zero_h_k<<<(2*NN*C1 + 255)/256, 256>>>(SB, 2*NN*C1);

    cudaLaunchAttribute pdl_attr;
    pdl_attr.id = cudaLaunchAttributeProgrammaticStreamSerialization;
    pdl_attr.val.programmaticStreamSerializationAllowed = 1;

    auto hop2 = [&](HopJob ja, HopJob jb) {
        cudaLaunchConfig_t cfg = {};
        cfg.gridDim = dim3((unsigned)(ja.nt + jb.nt));
        cfg.blockDim = dim3(256);
        cfg.attrs = &pdl_attr; cfg.numAttrs = 1;
        cudaLaunchKernelEx(&cfg, hop4_mma, ja, jb);
    };
    auto gate2 = [&](GateArgs ga, GateArgs gb) {
        cudaLaunchConfig_t cfg = {};
        cfg.gridDim = dim3((unsigned)(ga.nt + gb.nt));
        cfg.blockDim = dim3(128);
        cfg.attrs = &pdl_attr; cfg.numAttrs = 1;
        cudaLaunchKernelEx(&cfg, gate_mma, ga, gb);
    };

    // di pointer per step t
    auto dptr = [&](int t) -> const f16* {
        if (t < TIN)  return diAll + (size_t)t*NB;
        if (t == TIN) return diAll + (size_t)(TIN-1)*NB;
        return dih;
    };
    // stacked blocks 0=Wf,1=Wb,2=Wf2,3=Wb2; slice order [X,Wf,Wf2,Wb,Wb2]
    auto wire = [&](GateArgs& ga, const f16* in, const f16* s, size_t blk) {
        ga.Ah[0]=in;
        ga.Ah[1]=s;
        ga.Ah[2]=s+2*blk;
        ga.Ah[3]=s+blk;
        ga.Ah[4]=s+3*blk;
    };

    // ----- job builders -----
    auto A1 = [&](int t) -> HopJob {
        (void)t; return HopJob{SA, S12a, CH, (CH/64)*16};
    };
    auto A3 = [&](int t) -> HopJob {
        (void)t; return HopJob{T0a, T12a, CH, (CH/64)*16};
    };
    auto B1 = [&](int t) -> HopJob {
        size_t p = (size_t)(t & 1)*NN*C1;
        return HopJob{SB+p, S12b, C1, (C1/64)*16};
    };
    auto B3 = [&](int t) -> HopJob {
        (void)t; return HopJob{T0b, T12b, CH, (CH/64)*16};
    };
    auto A2 = [&](int t) -> GateArgs {
        GateArgs ga = {};
        wire(ga, SA, S12a, (size_t)NN*CH);
        for (int s=0;s<5;s++) ga.Bh[s]=ga.Ah[s];
        ga.strideA = HID; ga.strideB = HID; ga.split = HID; ga.Fp = HID; ga.nt = 256;
        ga.W1h = Wsh+OW0R; ga.b1 = br0; ga.Y1 = r0;
        ga.W2h = Wsh+OW0Z; ga.b2 = bz0; ga.Y2 = z0;
        ga.hmul = h0; ga.t0 = T0a;
        ga.dic = dptr(t); ga.Wd1 = Wdi + 0*5*HID; ga.Wd2 = Wdi + 1*5*HID;
        ga.mode = 0;
        return ga;
    };
    auto A4 = [&](int t) -> GateArgs {
        GateArgs ga = {};
        wire(ga, T0a, T12a, (size_t)NN*CH);
        for (int s=0;s<5;s++) ga.Bh[s]=ga.Ah[s];
        ga.strideA = HID; ga.strideB = HID; ga.split = HID; ga.Fp = HID; ga.nt = 128;
        ga.W1h = Wsh+OW0N; ga.b1 = bn0;
        ga.zg = z0; ga.h = h0;
        ga.e1 = SA; ga.e1s = HID; ga.e1o = 0;
        size_t p = (size_t)(t & 1)*NN*C1;
        ga.e2 = SB+p; ga.e2s = F1; ga.e2o = 0;
        ga.dic = dptr(t); ga.Wd1 = Wdi + 2*5*HID;
        ga.mode = 1;
        return ga;
    };
    auto B2 = [&](int t) -> GateArgs {
        GateArgs ga = {};
        size_t p = (size_t)(t & 1)*NN*C1;
        wire(ga, SB+p, S12b, (size_t)NN*C1);
        for (int s=0;s<5;s++) ga.Bh[s]=ga.Ah[s];
        ga.strideA = F1; ga.strideB = F1; ga.split = F1; ga.Fp = F1; ga.nt = 256;
        ga.W1h = Wsh+OW1R; ga.b1 = br1; ga.Y1 = r1;
        ga.W2h = Wsh+OW1Z; ga.b2 = bz1; ga.Y2 = z1;
        ga.hmul = h1; ga.t0 = T0b;
        ga.mode = 0;
        return ga;
    };
    auto B4 = [&](int t) -> GateArgs {
        GateArgs ga = {};
        size_t p = (size_t)(t & 1)*NN*C1;
        wire(ga, SB+p, S12b, (size_t)NN*C1);
        size_t blk = (size_t)NN*CH;
        ga.Bh[0]=T0b;
        ga.Bh[1]=T12b;
        ga.Bh[2]=T12b+2*blk;
        ga.Bh[3]=T12b+blk;
        ga.Bh[4]=T12b+3*blk;
        ga.strideA = F1; ga.strideB = HID; ga.split = HID; ga.Fp = F1; ga.nt = 128;
        ga.W1h = Wsh+OW1N; ga.b1 = bn1;
        ga.zg = z1; ga.h = h1;
        size_t pn = (size_t)((t + 1) & 1)*NN*C1;
        ga.e1 = SB+pn; ga.e1s = F1; ga.e1o = HID;
        if (t >= TIN) {
            ga.fuse = 2; ga.t = t - TIN;
            ga.Wp = Wp; ga.bp = bp; ga.out = out; ga.dO = dih;
        }
        ga.mode = 1;
        return ga;
    };

    auto zeroHop = [&](HopJob j) { j.nt = 0; return j; };
    auto zeroGate = [&](GateArgs g) { g.nt = 0; return g; };

    // ----- schedule -----
    // A(0)
    hop2(A1(0), zeroHop(A1(0)));
    gate2(A2(0), zeroGate(A2(0)));
    hop2(A3(0), zeroHop(A3(0)));
    gate2(A4(0), zeroGate(A4(0)));

    // encoder rounds: {B(j) || A(j+1)}, j=0..TIN-1 (A(TIN) = first decoder cell0)
    for (int j = 0; j < TIN; j++) {
        hop2(B1(j), A1(j+1));
        gate2(B2(j), A2(j+1));
        hop2(B3(j), A3(j+1));
        gate2(B4(j), A4(j+1));
    }

    // decoder rounds: A1 overlapped with B1; A2..A4 serial after B4 (di dep)
    for (int t = TIN; t < TIN + TOUT; t++) {
        bool last = (t == TIN + TOUT - 1);
        if (!last) hop2(B1(t), A1(t+1));
        else       hop2(B1(t), zeroHop(B1(t)));
        gate2(B2(t), zeroGate(B2(t)));
        hop2(B3(t), zeroHop(B3(t)));
        gate2(B4(t), zeroGate(B4(t)));
        if (!last) {
            gate2(A2(t+1), zeroGate(A2(t+1)));
            hop2(A3(t+1), zeroHop(A3(t+1)));
            gate2(A4(t+1), zeroGate(A4(t+1)));
        }
    }
}

// round 15
// speedup vs baseline: 1.1200x; 1.1200x over previous
#include <cuda_runtime.h>
#include <cuda_fp16.h>
#include <math.h>

// ---------------------------------------------------------------------------
// DCRNN 2-layer DCGRU. B=16, N=512, HID=64, K=2, T_in=12, T_out=12.
// Pure fp16 tensor-core GEMMs (fp32 accum). G4 = [Wf; Wb; Wf^2; Wb^2].
// R15: layer-0 di decoupled from hop chains (chains hop h only, C=1024/2048);
// di hop contributions U_s = G_s·di computed ONCE per step by a tiny dedicated
// GEMV kernel (encoder U's precomputed in setup); layer-0 gates add the di
// term in the epilogue from global U (10 loads + 20 FMA per thread).
// Decoder A1 overlaps with B1 (di off A1's path). Encoder fully pipelined.
// ---------------------------------------------------------------------------

#define NN   512
#define BB   16
#define HID  64
#define NB   (NN*BB)          // 8192
#define F1   128
#define C1   (BB*F1)          // 2048
#define CH   (BB*HID)         // 1024
#define TIN  12
#define TOUT 12

#define KC   32
#define APP  40
#define BPP  72
#define GAP  24
#define GBP  72

#define KP0  (5*HID)          // 320
#define KP1  (5*F1)           // 640

typedef __half f16;

// ---------------- device scratch -------------------------------------------
__device__ float g_G [4*NN*NN];
__device__ f16   g_Gh[4*NN*NN];
__device__ float g_cs[NN];
__device__ float g_h0[NB*HID];
__device__ float g_h1[NB*HID];
__device__ f16   g_SA [NN*CH];
__device__ f16   g_SB [2*NN*C1];
__device__ f16   g_S12a[4*NN*CH];
__device__ f16   g_S12b[4*NN*C1];
__device__ f16   g_T0a [NN*CH];
__device__ f16   g_T12a[4*NN*CH];
__device__ f16   g_T0b [NN*CH];
__device__ f16   g_T12b[4*NN*CH];
__device__ float g_r0[NB*HID];
__device__ float g_z0[NB*HID];
__device__ float g_r1[NB*HID];
__device__ float g_z1[NB*HID];
__device__ f16   g_diAll[TIN*NB];    // encoder di (fp16, node*16+b)
__device__ f16   g_dih[NB];          // decoder di (written by B4 proj)
__device__ float g_UAll[TIN*4*NB];   // encoder U_s (fp32)
__device__ float g_Ud[4*NB];         // decoder U_s
#define OW0R 0
#define OW0Z (KP0*HID)
#define OW0N (2*KP0*HID)
#define OW1R (3*KP0*HID)
#define OW1Z (3*KP0*HID + KP1*HID)
#define OW1N (3*KP0*HID + 2*KP1*HID)
#define WTOT (3*KP0*HID + 3*KP1*HID)
__device__ f16   g_Wsh[WTOT];
__device__ float g_Wdi[3*5*HID];     // di-weight rows: [r|z|n][5][64]

// ---------------- PTX helpers ----------------------------------------------
__device__ __forceinline__ void cp16(void* dst, const void* src) {
    unsigned d = (unsigned)__cvta_generic_to_shared(dst);
    asm volatile("cp.async.ca.shared.global [%0], [%1], 16;\n" :: "r"(d), "l"(src));
}
#define CP_COMMIT() asm volatile("cp.async.commit_group;\n")
#define CP_WAIT(n)  asm volatile("cp.async.wait_group %0;\n" :: "n"(n))

__device__ __forceinline__ void ldsm4(unsigned* r, const void* p) {
    unsigned a = (unsigned)__cvta_generic_to_shared(p);
    asm volatile("ldmatrix.sync.aligned.m8n8.x4.shared.b16 {%0,%1,%2,%3}, [%4];"
                 : "=r"(r[0]), "=r"(r[1]), "=r"(r[2]), "=r"(r[3]) : "r"(a));
}
__device__ __forceinline__ void ldsm4t(unsigned* r, const void* p) {
    unsigned a = (unsigned)__cvta_generic_to_shared(p);
    asm volatile("ldmatrix.sync.aligned.m8n8.x4.trans.shared.b16 {%0,%1,%2,%3}, [%4];"
                 : "=r"(r[0]), "=r"(r[1]), "=r"(r[2]), "=r"(r[3]) : "r"(a));
}
#define MMA_F16(d, a, b0v, b1v)                                               \
    asm("mma.sync.aligned.m16n8k16.row.col.f32.f16.f16.f32 "                  \
        "{%0,%1,%2,%3}, {%4,%5,%6,%7}, {%8,%9}, {%0,%1,%2,%3};"               \
        : "+f"(d[0]), "+f"(d[1]), "+f"(d[2]), "+f"(d[3])                      \
        : "r"(a[0]), "r"(a[1]), "r"(a[2]), "r"(a[3]), "r"(b0v), "r"(b1v))

__device__ __forceinline__ void store2(f16* Y, size_t off, float vx, float vy) {
    __half2 hh;
    hh.x = __float2half_rn(vx);
    hh.y = __float2half_rn(vy);
    *reinterpret_cast<__half2*>(&Y[off]) = hh;
}
__device__ __forceinline__ void emit1(float v, f16* X, size_t idx) {
    X[idx] = __float2half_rn(v);
}

// ---------------- setup kernels --------------------------------------------
__global__ void rownorm_k(const float* __restrict__ A, float* __restrict__ G) {
    int i = blockIdx.x;
    __shared__ float red[256];
    float s = 0.f;
    for (int j = threadIdx.x; j < NN; j += 256) s += A[i*NN + j];
    red[threadIdx.x] = s; __syncthreads();
    for (int off = 128; off; off >>= 1) {
        if (threadIdx.x < off) red[threadIdx.x] += red[threadIdx.x + off];
        __syncthreads();
    }
    float d = red[0] + 1e-6f;
    for (int j = threadIdx.x; j < NN; j += 256) G[i*NN + j] = A[i*NN + j] / d;
}
__global__ void colsum_k(const float* __restrict__ A, float* __restrict__ cs) {
    int c = blockIdx.x * blockDim.x + threadIdx.x;
    if (c < NN) {
        float s = 0.f;
        for (int r = 0; r < NN; r++) s += A[r*NN + c];
        cs[c] = s;
    }
}
__global__ void fill_wb_k(const float* __restrict__ A, const float* __restrict__ cs,
                          float* __restrict__ G) {
    int i = blockIdx.x;
    float d = cs[i] + 1e-6f;
    for (int j = threadIdx.x; j < NN; j += 256) G[(NN+i)*NN + j] = A[j*NN + i] / d;
}
__global__ void square_k(const float* __restrict__ G, float* __restrict__ Out) {
    const float* Am = G + (size_t)blockIdx.z*NN*NN;
    float* Cm = Out + (size_t)(2 + blockIdx.z)*NN*NN;
    const int m0 = blockIdx.y * 64, n0 = blockIdx.x * 64;
    const int tid = threadIdx.x;
    const int tx = tid & 15, ty = tid >> 4;
    __shared__ float As[16][64];
    __shared__ float Bs[16][64];
    float acc[4][4];
    #pragma unroll
    for (int i = 0; i < 4; i++)
        #pragma unroll
        for (int j = 0; j < 4; j++) acc[i][j] = 0.f;
    for (int k0 = 0; k0 < NN; k0 += 16) {
        {
            int m = tid >> 2, k4 = (tid & 3) * 4;
            float4 w = *reinterpret_cast<const float4*>(&Am[(size_t)(m0+m)*NN + k0 + k4]);
            As[k4+0][m] = w.x; As[k4+1][m] = w.y; As[k4+2][m] = w.z; As[k4+3][m] = w.w;
        }
        {
            int k = tid >> 4, c4 = (tid & 15) * 4;
            float4 v = *reinterpret_cast<const float4*>(&Am[(size_t)(k0+k)*NN + n0 + c4]);
            *reinterpret_cast<float4*>(&Bs[k][c4]) = v;
        }
        __syncthreads();
        #pragma unroll
        for (int k = 0; k < 16; k++) {
            float a[4], b[4];
            #pragma unroll
            for (int i = 0; i < 4; i++) a[i] = As[k][ty + 16*i];
            #pragma unroll
            for (int j = 0; j < 4; j++) b[j] = Bs[k][tx + 16*j];
            #pragma unroll
            for (int i = 0; i < 4; i++)
                #pragma unroll
                for (int j = 0; j < 4; j++) acc[i][j] += a[i] * b[j];
        }
        __syncthreads();
    }
    #pragma unroll
    for (int i = 0; i < 4; i++)
        #pragma unroll
        for (int j = 0; j < 4; j++)
            Cm[(size_t)(m0 + ty + 16*i)*NN + n0 + tx + 16*j] = acc[i][j];
}
__global__ void cvt_G_k(const float* __restrict__ G, f16* __restrict__ Gh) {
    int i = blockIdx.x * blockDim.x + threadIdx.x;
    if (i < 4*NN*NN) Gh[i] = __float2half_rn(G[i]);
}
__global__ void cvt_W0_k(const float* __restrict__ W, f16* __restrict__ Wh) {
    int i = blockIdx.x * blockDim.x + threadIdx.x;
    if (i >= KP0*HID) return;
    int row = i >> 6, c = i & 63;
    int s = row >> 6, f = row & 63;
    Wh[i] = __float2half_rn(W[(size_t)(s*65 + 1 + f)*HID + c]);
}
__global__ void cvt_Wdi_k(const float* __restrict__ W, float* __restrict__ out) {
    int i = blockIdx.x * blockDim.x + threadIdx.x;
    if (i < 5*HID) {
        int s = i >> 6, c = i & 63;
        out[i] = W[(size_t)(s*65)*HID + c];
    }
}
__global__ void cvt_W1_k(const float* __restrict__ W, f16* __restrict__ Wh) {
    int i = blockIdx.x * blockDim.x + threadIdx.x;
    if (i < KP1*HID) Wh[i] = __float2half_rn(W[i]);
}
__global__ void prep_di_k(const float* __restrict__ x, f16* __restrict__ diAll) {
    int i = blockIdx.x * blockDim.x + threadIdx.x;
    if (i >= TIN*NB) return;
    int t = i / NB, r = i - t*NB;
    int node = r >> 4, b = r & 15;
    diAll[i] = __float2half_rn(x[b*(TIN*NN) + t*NN + node]);
}
__global__ void zero2_k(float* a, float* b, int n) {
    int i = blockIdx.x * blockDim.x + threadIdx.x;
    if (i < n) { a[i] = 0.f; b[i] = 0.f; }
}
__global__ void zero_h_k(f16* a, int n) {
    int i = blockIdx.x * blockDim.x + threadIdx.x;
    if (i < n) a[i] = __float2half_rn(0.f);
}

// ---------------- tiny di-GEMV: U[s][node*16+b] = (G_blk(s) . di) ----------
// slice s=0..3 -> stacked block {0,2,1,3}. grid (64, nsteps), 256 threads.
__global__ void digemv_k(const f16* __restrict__ diBase, int diStride,
                         float* __restrict__ UBase, int uStride)
{
    const f16* di = diBase + (size_t)blockIdx.y * diStride;
    float* U = UBase + (size_t)blockIdx.y * uStride;
    __shared__ f16 dis[NB];
    const int tid = threadIdx.x;
    for (int i = tid; i < NB/8; i += 256) cp16(&dis[i*8], di + i*8);
    CP_COMMIT(); CP_WAIT(0);
    __syncthreads();
    const int si  = blockIdx.x & 3;
    const int nb0 = (blockIdx.x >> 2) * 32;
    const int blk = (0x3120 >> (si*4)) & 0xF;
    for (int o = tid; o < 512; o += 256) {
        int node = nb0 + (o >> 4), b = o & 15;
        const __half2* grow = reinterpret_cast<const __half2*>(
            g_Gh + (size_t)(blk*NN + node)*NN);
        float acc = 0.f;
        #pragma unroll 8
        for (int k2 = 0; k2 < NN/2; k2++) {
            float2 gv = __half22float2(grow[k2]);
            acc += gv.x * __half2float(dis[(2*k2)*16 + b]);
            acc += gv.y * __half2float(dis[(2*k2+1)*16 + b]);
        }
        U[si*NB + node*16 + b] = acc;
    }
}

// ---------------- stacked hop GEMM, dual-job, pure fp16 --------------------
struct HopJob {
    const f16* X;
    f16* Y;
    int C, nt;
};

__global__ __launch_bounds__(256, 4)
void hop4_mma(HopJob j0, HopJob j1)
{
    const int tile = blockIdx.x;
    HopJob J; int lt;
    if (tile < j0.nt) { J = j0; lt = tile; }
    else              { J = j1; lt = tile - j0.nt; }
    const int m0 = (lt & 15) << 7;
    const int c0 = (lt >> 4) << 6;
    const int C = J.C;

    __shared__ f16 Ash[2][128][APP];
    __shared__ f16 Bsh[2][KC][BPP];

    const int tid = threadIdx.x;
    const int wid = tid >> 5, lane = tid & 31;
    const int wm = (wid >> 1) * 32;
    const int wn = (wid & 1) * 32;
    const int g = lane >> 2, t4 = lane & 3;
    const int ar = tid >> 1, aj = (tid & 1) * 16;
    const int bk = tid >> 3, bj = (tid & 7) * 8;

    float acc[2][4][4];
    #pragma unroll
    for (int mi = 0; mi < 2; mi++)
        #pragma unroll
        for (int ni = 0; ni < 4; ni++)
            #pragma unroll
            for (int q = 0; q < 4; q++) acc[mi][ni][q] = 0.f;

    auto load_A = [&](int buf, int k0) {
        const f16* a1 = g_Gh + (size_t)(m0+ar)*NN + k0 + aj;
        cp16(&Ash[buf][ar][aj],   a1);
        cp16(&Ash[buf][ar][aj+8], a1+8);
    };
    auto load_B = [&](int buf, int k0) {
        cp16(&Bsh[buf][bk][bj], J.X + (size_t)(k0+bk)*C + c0 + bj);
    };

    load_A(0, 0);
#if __CUDA_ARCH__ >= 900
    cudaGridDependencySynchronize();
#endif
    load_B(0, 0);
    CP_COMMIT();

    const int NIT = NN / KC;
    for (int it = 0; it < NIT; it++) {
        int buf = it & 1;
        if (it + 1 < NIT) {
            load_A(buf ^ 1, (it+1)*KC);
            load_B(buf ^ 1, (it+1)*KC);
            CP_COMMIT(); CP_WAIT(1);
        } else {
            CP_WAIT(0);
        }
        __syncthreads();

        #pragma unroll
        for (int kk = 0; kk < KC; kk += 16) {
            const int arow = lane & 15;
            const int acol = kk + ((lane >> 4) << 3);
            unsigned ah[2][4];
            #pragma unroll
            for (int mi = 0; mi < 2; mi++)
                ldsm4(ah[mi], &Ash[buf][wm + mi*16 + arow][acol]);
            const int brow = kk + (lane & 15);
            #pragma unroll
            for (int np = 0; np < 2; np++) {
                const int bcol = wn + np*16 + ((lane >> 4) << 3);
                unsigned bh[4];
                ldsm4t(bh, &Bsh[buf][brow][bcol]);
                #pragma unroll
                for (int h2 = 0; h2 < 2; h2++) {
                    int ni = np*2 + h2;
                    #pragma unroll
                    for (int mi = 0; mi < 2; mi++)
                        MMA_F16(acc[mi][ni], ah[mi], bh[h2*2], bh[h2*2+1]);
                }
            }
        }
        __syncthreads();
    }

    #pragma unroll
    for (int mi = 0; mi < 2; mi++) {
        #pragma unroll
        for (int ni = 0; ni < 4; ni++) {
            int ncol = c0 + wn + ni*8 + t4*2;
            int m1 = m0 + wm + mi*16 + g;
            store2(J.Y, (size_t)m1*C + ncol,     acc[mi][ni][0], acc[mi][ni][1]);
            store2(J.Y, (size_t)(m1+8)*C + ncol, acc[mi][ni][2], acc[mi][ni][3]);
        }
    }
}

// ---------------- gate GEMM, dual-job, fp16 + epilogue di term -------------
struct GateArgs {
    const f16 *Ah[5];
    const f16 *Bh[5];
    int strideA, strideB, split, Fp, nt;
    const f16 *W1h; const float* b1; float* Y1;
    const f16 *W2h; const float* b2; float* Y2;
    const float* zg; float* h;
    const float* hmul; f16* t0;
    f16* e1; int e1s, e1o;
    f16* e2; int e2s, e2o;
    const f16* dic;                  // di vector (NB fp16) or null (layer1)
    const float* U;                  // [4][NB] hop contributions of di
    const float *Wd1, *Wd2;          // [5][64] di weight rows per gate
    int fuse, t;                     // fuse==2: decoder proj -> out + dO
    const float *Wp, *bp; float* out;
    f16* dO;
    int mode;
};

__global__ __launch_bounds__(128, 4)
void gate_mma(GateArgs a0, GateArgs a1)
{
    const int tile = blockIdx.x;
    const GateArgs& a = (tile < a0.nt) ? a0 : a1;
    const int lt = (tile < a0.nt) ? tile : tile - a0.nt;
    const int zsel = lt >> 7;
    const int m0 = (lt & 127) << 6;

    const f16* Wh = (a.mode == 0 && zsel) ? a.W2h : a.W1h;
    const float* bl = (a.mode == 0 && zsel) ? a.b2 : a.b1;
    float* Yl = (a.mode == 0 && zsel) ? a.Y2 : a.Y1;

    const int tid = threadIdx.x;
    const int wid = tid >> 5, lane = tid & 31;
    const int g = lane >> 2, t4 = lane & 3;
    const int CPS = a.Fp >> 4;

    __shared__ f16 Ash[2][64][GAP];
    __shared__ f16 Bsh[2][16][GBP];

    float acc[8][4];
    #pragma unroll
    for (int ni = 0; ni < 8; ni++)
        #pragma unroll
        for (int q = 0; q < 4; q++) acc[ni][q] = 0.f;

    const int arw = tid >> 1, ja = (tid & 1) * 8;
    const int bkr = tid >> 3, bjc = (tid & 7) * 8;

    auto load_W = [&](int buf, int kidx) {
        int gk = kidx*16 + bkr;
        cp16(&Bsh[buf][bkr][bjc], Wh + (size_t)gk*HID + bjc);
    };
    auto load_X = [&](int buf, int kidx) {
        int s = kidx / CPS;
        int f0 = (kidx - s*CPS)*16 + ja;
        const f16* sh;
        if (f0 < a.split) sh = a.Ah[s] + (size_t)(m0+arw)*a.strideA + f0;
        else              sh = a.Bh[s] + (size_t)(m0+arw)*a.strideB + (f0 - a.split);
        cp16(&Ash[buf][arw][ja], sh);
    };

    load_W(0, 0);
#if __CUDA_ARCH__ >= 900
    cudaGridDependencySynchronize();
#endif
    load_X(0, 0);
    CP_COMMIT();

    const int NIT = 5 * CPS;
    for (int it = 0; it < NIT; it++) {
        int buf = it & 1;
        if (it + 1 < NIT) {
            load_W(buf ^ 1, it+1);
            load_X(buf ^ 1, it+1);
            CP_COMMIT(); CP_WAIT(1);
        } else {
            CP_WAIT(0);
        }
        __syncthreads();

        const int arow = lane & 15;
        const int acol = (lane >> 4) << 3;
        unsigned ah[4];
        ldsm4(ah, &Ash[buf][wid*16 + arow][acol]);
        const int brow = lane & 15;
        #pragma unroll
        for (int np = 0; np < 4; np++) {
            const int bcol = np*16 + ((lane >> 4) << 3);
            unsigned bh[4];
            ldsm4t(bh, &Bsh[buf][brow][bcol]);
            #pragma unroll
            for (int h2 = 0; h2 < 2; h2++) {
                int ni = np*2 + h2;
                MMA_F16(acc[ni], ah, bh[h2*2], bh[h2*2+1]);
            }
        }
        __syncthreads();
    }

    // per-row di terms (hoisted: m depends only on half)
    float dv[2][5];
    const float* Wd = nullptr;
    if (a.dic) {
        Wd = (a.mode == 0 && zsel) ? a.Wd2 : a.Wd1;
        #pragma unroll
        for (int half = 0; half < 2; half++) {
            int m = m0 + wid*16 + g + half*8;
            dv[half][0] = __half2float(a.dic[m]);
            #pragma unroll
            for (int s = 0; s < 4; s++) dv[half][s+1] = a.U[s*NB + m];
        }
    }

    const bool write_t0 = (a.mode == 0) && (zsel == 0) && (a.t0 != nullptr);
    float partial[2] = {0.f, 0.f};
    #pragma unroll
    for (int ni = 0; ni < 8; ni++) {
        int c = ni*8 + t4*2;
        float b0 = bl[c], b1v = bl[c+1];
        #pragma unroll
        for (int half = 0; half < 2; half++) {
            int m = m0 + wid*16 + g + half*8;
            float vx = acc[ni][half*2]   + b0;
            float vy = acc[ni][half*2+1] + b1v;
            if (a.dic) {
                vx += dv[half][0]*Wd[c]     + dv[half][1]*Wd[64+c]
                    + dv[half][2]*Wd[128+c] + dv[half][3]*Wd[192+c]
                    + dv[half][4]*Wd[256+c];
                vy += dv[half][0]*Wd[c+1]     + dv[half][1]*Wd[64+c+1]
                    + dv[half][2]*Wd[128+c+1] + dv[half][3]*Wd[192+c+1]
                    + dv[half][4]*Wd[256+c+1];
            }
            size_t off = (size_t)m*HID + c;
            if (a.mode == 0) {
                float2 o;
                o.x = 1.f / (1.f + expf(-vx));
                o.y = 1.f / (1.f + expf(-vy));
                *reinterpret_cast<float2*>(&Yl[off]) = o;
                if (write_t0) {
                    float2 hh = *reinterpret_cast<const float2*>(&a.hmul[off]);
                    store2(a.t0, off, o.x * hh.x, o.y * hh.y);
                }
            } else {
                float2 zz = *reinterpret_cast<const float2*>(&a.zg[off]);
                float2 hh = *reinterpret_cast<float2*>(&a.h[off]);
                float2 o;
                o.x = (1.f - zz.x) * hh.x + zz.x * tanhf(vx);
                o.y = (1.f - zz.y) * hh.y + zz.y * tanhf(vy);
                *reinterpret_cast<float2*>(&a.h[off]) = o;
                if (a.e1) store2(a.e1, (size_t)m*a.e1s + a.e1o + c, o.x, o.y);
                if (a.e2) store2(a.e2, (size_t)m*a.e2s + a.e2o + c, o.x, o.y);
                if (a.fuse == 2) partial[half] += o.x * a.Wp[c] + o.y * a.Wp[c+1];
            }
        }
    }

    if (a.mode == 1 && a.fuse == 2) {
        #pragma unroll
        for (int half = 0; half < 2; half++) {
            float p = partial[half];
            p += __shfl_xor_sync(0xffffffffu, p, 1);
            p += __shfl_xor_sync(0xffffffffu, p, 2);
            int m = m0 + wid*16 + g + half*8;
            if (t4 == 0) {
                int node = m >> 4, b = m & 15;
                float s = p + a.bp[0];
                a.out[b*(TOUT*NN) + a.t*NN + node] = s;
                emit1(s, a.dO, (size_t)m);
            }
        }
    }
}

// ---------------- host driver ----------------------------------------------
extern "C" void kernel_launch(void* const* d_in, const int* in_sizes, int n_in,
                              void* d_out, int out_size)
{
    const float* x   = (const float*)d_in[0];
    const float* A   = (const float*)d_in[1];
    const float* Wr0 = (const float*)d_in[2];
    const float* br0 = (const float*)d_in[3];
    const float* Wz0 = (const float*)d_in[4];
    const float* bz0 = (const float*)d_in[5];
    const float* Wn0 = (const float*)d_in[6];
    const float* bn0 = (const float*)d_in[7];
    const float* Wr1 = (const float*)d_in[8];
    const float* br1 = (const float*)d_in[9];
    const float* Wz1 = (const float*)d_in[10];
    const float* bz1 = (const float*)d_in[11];
    const float* Wn1 = (const float*)d_in[12];
    const float* bn1 = (const float*)d_in[13];
    const float* Wp  = (const float*)d_in[14];
    const float* bp  = (const float*)d_in[15];
    float* out = (float*)d_out;

    float *G, *cs, *h0, *h1, *r0, *z0, *r1, *z1, *Wdi, *UAll, *Ud;
    f16 *Gh, *SA, *SB, *S12a, *S12b, *T0a, *T12a, *T0b, *T12b, *Wsh, *diAll, *dih;
    cudaGetSymbolAddress((void**)&G,     g_G);
    cudaGetSymbolAddress((void**)&Gh,    g_Gh);
    cudaGetSymbolAddress((void**)&cs,    g_cs);
    cudaGetSymbolAddress((void**)&h0,    g_h0);
    cudaGetSymbolAddress((void**)&h1,    g_h1);
    cudaGetSymbolAddress((void**)&SA,    g_SA);
    cudaGetSymbolAddress((void**)&SB,    g_SB);
    cudaGetSymbolAddress((void**)&S12a,  g_S12a);
    cudaGetSymbolAddress((void**)&S12b,  g_S12b);
    cudaGetSymbolAddress((void**)&T0a,   g_T0a);
    cudaGetSymbolAddress((void**)&T12a,  g_T12a);
    cudaGetSymbolAddress((void**)&T0b,   g_T0b);
    cudaGetSymbolAddress((void**)&T12b,  g_T12b);
    cudaGetSymbolAddress((void**)&r0,    g_r0);
    cudaGetSymbolAddress((void**)&z0,    g_z0);
    cudaGetSymbolAddress((void**)&r1,    g_r1);
    cudaGetSymbolAddress((void**)&z1,    g_z1);
    cudaGetSymbolAddress((void**)&Wsh,   g_Wsh);
    cudaGetSymbolAddress((void**)&Wdi,   g_Wdi);
    cudaGetSymbolAddress((void**)&diAll, g_diAll);
    cudaGetSymbolAddress((void**)&dih,   g_dih);
    cudaGetSymbolAddress((void**)&UAll,  g_UAll);
    cudaGetSymbolAddress((void**)&Ud,    g_Ud);

    rownorm_k<<<NN, 256>>>(A, G);
    colsum_k<<<2, 256>>>(A, cs);
    fill_wb_k<<<NN, 256>>>(A, cs, G);
    square_k<<<dim3(8, 8, 2), 256>>>(G, G);
    cvt_G_k<<<(4*NN*NN + 255)/256, 256>>>(G, Gh);
    int g0 = (KP0*HID + 255)/256, g1 = (KP1*HID + 255)/256;
    cvt_W0_k<<<g0, 256>>>(Wr0, Wsh + OW0R);
    cvt_W0_k<<<g0, 256>>>(Wz0, Wsh + OW0Z);
    cvt_W0_k<<<g0, 256>>>(Wn0, Wsh + OW0N);
    cvt_W1_k<<<g1, 256>>>(Wr1, Wsh + OW1R);
    cvt_W1_k<<<g1, 256>>>(Wz1, Wsh + OW1Z);
    cvt_W1_k<<<g1, 256>>>(Wn1, Wsh + OW1N);
    cvt_Wdi_k<<<2, 256>>>(Wr0, Wdi + 0*5*HID);
    cvt_Wdi_k<<<2, 256>>>(Wz0, Wdi + 1*5*HID);
    cvt_Wdi_k<<<2, 256>>>(Wn0, Wdi + 2*5*HID);
    prep_di_k<<<(TIN*NB + 255)/256, 256>>>(x, diAll);
    digemv_k<<<dim3(64, TIN), 256>>>(diAll, NB, UAll, 4*NB);
    zero2_k<<<(NB*HID + 255)/256, 256>>>(h0, h1, NB*HID);
    zero_h_k<<<(NN*CH + 255)/256, 256>>>(SA, NN*CH);
    zero_h_k<<<(2*NN*C1 + 255)/256, 256>>>(SB, 2*NN*C1);

    cudaLaunchAttribute pdl_attr;
    pdl_attr.id = cudaLaunchAttributeProgrammaticStreamSerialization;
    pdl_attr.val.programmaticStreamSerializationAllowed = 1;

    auto hop2 = [&](HopJob ja, HopJob jb) {
        cudaLaunchConfig_t cfg = {};
        cfg.gridDim = dim3((unsigned)(ja.nt + jb.nt));
        cfg.blockDim = dim3(256);
        cfg.attrs = &pdl_attr; cfg.numAttrs = 1;
        cudaLaunchKernelEx(&cfg, hop4_mma, ja, jb);
    };
    auto gate2 = [&](GateArgs ga, GateArgs gb) {
        cudaLaunchConfig_t cfg = {};
        cfg.gridDim = dim3((unsigned)(ga.nt + gb.nt));
        cfg.blockDim = dim3(128);
        cfg.attrs = &pdl_attr; cfg.numAttrs = 1;
        cudaLaunchKernelEx(&cfg, gate_mma, ga, gb);
    };

    auto dptr = [&](int t) -> const f16* {
        if (t < TIN)  return diAll + (size_t)t*NB;
        if (t == TIN) return diAll + (size_t)(TIN-1)*NB;
        return dih;
    };
    auto uptr = [&](int t) -> const float* {
        if (t < TIN)  return UAll + (size_t)t*4*NB;
        if (t == TIN) return UAll + (size_t)(TIN-1)*4*NB;
        return Ud;
    };
    auto wire = [&](GateArgs& ga, const f16* in, const f16* s, size_t blk) {
        ga.Ah[0]=in;
        ga.Ah[1]=s;
        ga.Ah[2]=s+2*blk;
        ga.Ah[3]=s+blk;
        ga.Ah[4]=s+3*blk;
    };

    // ----- job builders -----
    auto A1 = [&](int t) -> HopJob {
        (void)t; return HopJob{SA, S12a, CH, (CH/64)*16};
    };
    auto A3 = [&](int t) -> HopJob {
        (void)t; return HopJob{T0a, T12a, CH, (CH/64)*16};
    };
    auto B1 = [&](int t) -> HopJob {
        size_t p = (size_t)(t & 1)*NN*C1;
        return HopJob{SB+p, S12b, C1, (C1/64)*16};
    };
    auto B3 = [&](int t) -> HopJob {
        (void)t; return HopJob{T0b, T12b, CH, (CH/64)*16};
    };
    auto A2 = [&](int t) -> GateArgs {
        GateArgs ga = {};
        wire(ga, SA, S12a, (size_t)NN*CH);
        for (int s=0;s<5;s++) ga.Bh[s]=ga.Ah[s];
        ga.strideA = HID; ga.strideB = HID; ga.split = HID; ga.Fp = HID; ga.nt = 256;
        ga.W1h = Wsh+OW0R; ga.b1 = br0; ga.Y1 = r0;
        ga.W2h = Wsh+OW0Z; ga.b2 = bz0; ga.Y2 = z0;
        ga.hmul = h0; ga.t0 = T0a;
        ga.dic = dptr(t); ga.U = uptr(t);
        ga.Wd1 = Wdi + 0*5*HID; ga.Wd2 = Wdi + 1*5*HID;
        ga.mode = 0;
        return ga;
    };
    auto A4 = [&](int t) -> GateArgs {
        GateArgs ga = {};
        wire(ga, T0a, T12a, (size_t)NN*CH);
        for (int s=0;s<5;s++) ga.Bh[s]=ga.Ah[s];
        ga.strideA = HID; ga.strideB = HID; ga.split = HID; ga.Fp = HID; ga.nt = 128;
        ga.W1h = Wsh+OW0N; ga.b1 = bn0;
        ga.zg = z0; ga.h = h0;
        ga.e1 = SA; ga.e1s = HID; ga.e1o = 0;
        size_t p = (size_t)(t & 1)*NN*C1;
        ga.e2 = SB+p; ga.e2s = F1; ga.e2o = 0;
        ga.dic = dptr(t); ga.U = uptr(t);
        ga.Wd1 = Wdi + 2*5*HID;
        ga.mode = 1;
        return ga;
    };
    auto B2 = [&](int t) -> GateArgs {
        GateArgs ga = {};
        size_t p = (size_t)(t & 1)*NN*C1;
        wire(ga, SB+p, S12b, (size_t)NN*C1);
        for (int s=0;s<5;s++) ga.Bh[s]=ga.Ah[s];
        ga.strideA = F1; ga.strideB = F1; ga.split = F1; ga.Fp = F1; ga.nt = 256;
        ga.W1h = Wsh+OW1R; ga.b1 = br1; ga.Y1 = r1;
        ga.W2h = Wsh+OW1Z; ga.b2 = bz1; ga.Y2 = z1;
        ga.hmul = h1; ga.t0 = T0b;
        ga.mode = 0;
        return ga;
    };
    auto B4 = [&](int t) -> GateArgs {
        GateArgs ga = {};
        size_t p = (size_t)(t & 1)*NN*C1;
        wire(ga, SB+p, S12b, (size_t)NN*C1);
        size_t blk = (size_t)NN*CH;
        ga.Bh[0]=T0b;
        ga.Bh[1]=T12b;
        ga.Bh[2]=T12b+2*blk;
        ga.Bh[3]=T12b+blk;
        ga.Bh[4]=T12b+3*blk;
        ga.strideA = F1; ga.strideB = HID; ga.split = HID; ga.Fp = F1; ga.nt = 128;
        ga.W1h = Wsh+OW1N; ga.b1 = bn1;
        ga.zg = z1; ga.h = h1;
        size_t pn = (size_t)((t + 1) & 1)*NN*C1;
        ga.e1 = SB+pn; ga.e1s = F1; ga.e1o = HID;
        if (t >= TIN) {
            ga.fuse = 2; ga.t = t - TIN;
            ga.Wp = Wp; ga.bp = bp; ga.out = out; ga.dO = dih;
        }
        ga.mode = 1;
        return ga;
    };

    auto zeroHop = [&](HopJob j) { j.nt = 0; return j; };
    auto zeroGate = [&](GateArgs g) { g.nt = 0; return g; };

    // ----- schedule -----
    // A(0)
    hop2(A1(0), zeroHop(A1(0)));
    gate2(A2(0), zeroGate(A2(0)));
    hop2(A3(0), zeroHop(A3(0)));
    gate2(A4(0), zeroGate(A4(0)));

    // encoder rounds: {B(j) || A(j+1)}, j=0..TIN-1 (A(TIN) = first decoder cell0)
    for (int j = 0; j < TIN; j++) {
        hop2(B1(j), A1(j+1));
        gate2(B2(j), A2(j+1));
        hop2(B3(j), A3(j+1));
        gate2(B4(j), A4(j+1));
    }

    // decoder rounds: A1 overlapped with B1; digemv + A2..A4 after B4
    for (int t = TIN; t < TIN + TOUT; t++) {
        bool last = (t == TIN + TOUT - 1);
        if (!last) hop2(B1(t), A1(t+1));
        else       hop2(B1(t), zeroHop(B1(t)));
        gate2(B2(t), zeroGate(B2(t)));
        hop2(B3(t), zeroHop(B3(t)));
        gate2(B4(t), zeroGate(B4(t)));
        if (!last) {
            digemv_k<<<dim3(64, 1), 256>>>(dih, 0, Ud, 0);
            gate2(A2(t+1), zeroGate(A2(t+1)));
            hop2(A3(t+1), zeroHop(A3(t+1)));
            gate2(A4(t+1), zeroGate(A4(t+1)));
        }
    }
}

// round 16
// speedup vs baseline: 1.2341x; 1.1019x over previous
#include <cuda_runtime.h>
#include <cuda_fp16.h>
#include <math.h>

// ---------------------------------------------------------------------------
// DCRNN 2-layer DCGRU. B=16, N=512, HID=64, K=2, T_in=12, T_out=12.
// Pure fp16 tensor-core GEMMs (fp32 accum). G4 = [Wf; Wb; Wf^2; Wb^2].
// R16 = R13 structure (best) + gate mainloop processes K=32/iteration
// (two 16-subchunks), halving barrier/wait counts on the critical path.
// ---------------------------------------------------------------------------

#define NN   512
#define BB   16
#define HID  64
#define NB   (NN*BB)          // 8192
#define F0S  72               // layer0 storage: [h(64) | di | pad(7)]
#define F0P  80               // layer0 gate K per slice (rows 65..79 zero wt)
#define F1   128
#define C0S  (BB*F0S)         // 1152
#define C1   (BB*F1)          // 2048
#define CH   (BB*HID)         // 1024
#define TIN  12
#define TOUT 12

#define KC   32
#define APP  40
#define BPP  72
#define GAP  40               // gate A smem pitch (32 + 8)
#define GBP  72

#define KP0  (5*F0P)          // 400
#define KP1  (5*F1)           // 640

typedef __half f16;

// ---------------- device scratch -------------------------------------------
__device__ float g_G [4*NN*NN];
__device__ f16   g_Gh[4*NN*NN];
__device__ float g_cs[NN];
__device__ float g_h0[NB*HID];
__device__ float g_h1[NB*HID];
__device__ f16   g_SA [NN*C0S];
__device__ f16   g_SB [2*NN*C1];     // step-parity double buffer [h0|h1]
__device__ f16   g_S12a[4*NN*C0S];
__device__ f16   g_S12b[4*NN*C1];
__device__ f16   g_T0a [NN*CH];
__device__ f16   g_T12a[4*NN*CH];
__device__ f16   g_T0b [NN*CH];
__device__ f16   g_T12b[4*NN*CH];
__device__ float g_r0[NB*HID];
__device__ float g_z0[NB*HID];
__device__ float g_r1[NB*HID];
__device__ float g_z1[NB*HID];
__device__ f16   g_diAll[TIN*NB];
__device__ f16   g_dih[NB];
#define OW0R 0
#define OW0Z (KP0*HID)
#define OW0N (2*KP0*HID)
#define OW1R (3*KP0*HID)
#define OW1Z (3*KP0*HID + KP1*HID)
#define OW1N (3*KP0*HID + 2*KP1*HID)
#define WTOT (3*KP0*HID + 3*KP1*HID)
__device__ f16   g_Wsh[WTOT];

// ---------------- PTX helpers ----------------------------------------------
__device__ __forceinline__ void cp16(void* dst, const void* src) {
    unsigned d = (unsigned)__cvta_generic_to_shared(dst);
    asm volatile("cp.async.ca.shared.global [%0], [%1], 16;\n" :: "r"(d), "l"(src));
}
#define CP_COMMIT() asm volatile("cp.async.commit_group;\n")
#define CP_WAIT(n)  asm volatile("cp.async.wait_group %0;\n" :: "n"(n))

__device__ __forceinline__ void ldsm4(unsigned* r, const void* p) {
    unsigned a = (unsigned)__cvta_generic_to_shared(p);
    asm volatile("ldmatrix.sync.aligned.m8n8.x4.shared.b16 {%0,%1,%2,%3}, [%4];"
                 : "=r"(r[0]), "=r"(r[1]), "=r"(r[2]), "=r"(r[3]) : "r"(a));
}
__device__ __forceinline__ void ldsm4t(unsigned* r, const void* p) {
    unsigned a = (unsigned)__cvta_generic_to_shared(p);
    asm volatile("ldmatrix.sync.aligned.m8n8.x4.trans.shared.b16 {%0,%1,%2,%3}, [%4];"
                 : "=r"(r[0]), "=r"(r[1]), "=r"(r[2]), "=r"(r[3]) : "r"(a));
}
#define MMA_F16(d, a, b0v, b1v)                                               \
    asm("mma.sync.aligned.m16n8k16.row.col.f32.f16.f16.f32 "                  \
        "{%0,%1,%2,%3}, {%4,%5,%6,%7}, {%8,%9}, {%0,%1,%2,%3};"               \
        : "+f"(d[0]), "+f"(d[1]), "+f"(d[2]), "+f"(d[3])                      \
        : "r"(a[0]), "r"(a[1]), "r"(a[2]), "r"(a[3]), "r"(b0v), "r"(b1v))

__device__ __forceinline__ void store2(f16* Y, size_t off, float vx, float vy) {
    __half2 hh;
    hh.x = __float2half_rn(vx);
    hh.y = __float2half_rn(vy);
    *reinterpret_cast<__half2*>(&Y[off]) = hh;
}
__device__ __forceinline__ void emit1(float v, f16* X, size_t idx) {
    X[idx] = __float2half_rn(v);
}

// ---------------- setup kernels --------------------------------------------
__global__ void rownorm_k(const float* __restrict__ A, float* __restrict__ G) {
    int i = blockIdx.x;
    __shared__ float red[256];
    float s = 0.f;
    for (int j = threadIdx.x; j < NN; j += 256) s += A[i*NN + j];
    red[threadIdx.x] = s; __syncthreads();
    for (int off = 128; off; off >>= 1) {
        if (threadIdx.x < off) red[threadIdx.x] += red[threadIdx.x + off];
        __syncthreads();
    }
    float d = red[0] + 1e-6f;
    for (int j = threadIdx.x; j < NN; j += 256) G[i*NN + j] = A[i*NN + j] / d;
}
__global__ void colsum_k(const float* __restrict__ A, float* __restrict__ cs) {
    int c = blockIdx.x * blockDim.x + threadIdx.x;
    if (c < NN) {
        float s = 0.f;
        for (int r = 0; r < NN; r++) s += A[r*NN + c];
        cs[c] = s;
    }
}
__global__ void fill_wb_k(const float* __restrict__ A, const float* __restrict__ cs,
                          float* __restrict__ G) {
    int i = blockIdx.x;
    float d = cs[i] + 1e-6f;
    for (int j = threadIdx.x; j < NN; j += 256) G[(NN+i)*NN + j] = A[j*NN + i] / d;
}
__global__ void square_k(const float* __restrict__ G, float* __restrict__ Out) {
    const float* Am = G + (size_t)blockIdx.z*NN*NN;
    float* Cm = Out + (size_t)(2 + blockIdx.z)*NN*NN;
    const int m0 = blockIdx.y * 64, n0 = blockIdx.x * 64;
    const int tid = threadIdx.x;
    const int tx = tid & 15, ty = tid >> 4;
    __shared__ float As[16][64];
    __shared__ float Bs[16][64];
    float acc[4][4];
    #pragma unroll
    for (int i = 0; i < 4; i++)
        #pragma unroll
        for (int j = 0; j < 4; j++) acc[i][j] = 0.f;
    for (int k0 = 0; k0 < NN; k0 += 16) {
        {
            int m = tid >> 2, k4 = (tid & 3) * 4;
            float4 w = *reinterpret_cast<const float4*>(&Am[(size_t)(m0+m)*NN + k0 + k4]);
            As[k4+0][m] = w.x; As[k4+1][m] = w.y; As[k4+2][m] = w.z; As[k4+3][m] = w.w;
        }
        {
            int k = tid >> 4, c4 = (tid & 15) * 4;
            float4 v = *reinterpret_cast<const float4*>(&Am[(size_t)(k0+k)*NN + n0 + c4]);
            *reinterpret_cast<float4*>(&Bs[k][c4]) = v;
        }
        __syncthreads();
        #pragma unroll
        for (int k = 0; k < 16; k++) {
            float a[4], b[4];
            #pragma unroll
            for (int i = 0; i < 4; i++) a[i] = As[k][ty + 16*i];
            #pragma unroll
            for (int j = 0; j < 4; j++) b[j] = Bs[k][tx + 16*j];
            #pragma unroll
            for (int i = 0; i < 4; i++)
                #pragma unroll
                for (int j = 0; j < 4; j++) acc[i][j] += a[i] * b[j];
        }
        __syncthreads();
    }
    #pragma unroll
    for (int i = 0; i < 4; i++)
        #pragma unroll
        for (int j = 0; j < 4; j++)
            Cm[(size_t)(m0 + ty + 16*i)*NN + n0 + tx + 16*j] = acc[i][j];
}
__global__ void cvt_G_k(const float* __restrict__ G, f16* __restrict__ Gh) {
    int i = blockIdx.x * blockDim.x + threadIdx.x;
    if (i < 4*NN*NN) Gh[i] = __float2half_rn(G[i]);
}
__global__ void cvt_W0_k(const float* __restrict__ W, f16* __restrict__ Wh) {
    int i = blockIdx.x * blockDim.x + threadIdx.x;
    if (i >= KP0*HID) return;
    int row = i >> 6, c = i & 63;
    int s = row / F0P, f = row - s*F0P;
    float v = 0.f;
    if (f < 64)       v = W[(size_t)(s*65 + f + 1)*HID + c];
    else if (f == 64) v = W[(size_t)(s*65)*HID + c];
    Wh[i] = __float2half_rn(v);
}
__global__ void cvt_W1_k(const float* __restrict__ W, f16* __restrict__ Wh) {
    int i = blockIdx.x * blockDim.x + threadIdx.x;
    if (i < KP1*HID) Wh[i] = __float2half_rn(W[i]);
}
__global__ void zero2_k(float* a, float* b, int n) {
    int i = blockIdx.x * blockDim.x + threadIdx.x;
    if (i < n) { a[i] = 0.f; b[i] = 0.f; }
}
__global__ void zero_h_k(f16* a, int n) {
    int i = blockIdx.x * blockDim.x + threadIdx.x;
    if (i < n) a[i] = __float2half_rn(0.f);
}
__global__ void copy_xt(const float* __restrict__ x, int t, f16* __restrict__ SA)
{
    int idx = blockIdx.x * blockDim.x + threadIdx.x;
    if (idx >= NB) return;
    int b = idx >> 9, n = idx & 511;
    float v = x[b*(TIN*NN) + t*NN + n];
    int m = n*BB + b;
    emit1(v, SA, (size_t)m*F0S + 64);
}

// ---------------- stacked hop GEMM, dual-job, pure fp16 --------------------
struct HopJob {
    const f16* X;
    f16* Y;
    int C, nt;
};

__global__ __launch_bounds__(256, 4)
void hop4_mma(HopJob j0, HopJob j1)
{
    const int tile = blockIdx.x;
    HopJob J; int lt;
    if (tile < j0.nt) { J = j0; lt = tile; }
    else              { J = j1; lt = tile - j0.nt; }
    const int m0 = (lt & 15) << 7;
    const int c0 = (lt >> 4) << 6;
    const int C = J.C;

    __shared__ f16 Ash[2][128][APP];
    __shared__ f16 Bsh[2][KC][BPP];

    const int tid = threadIdx.x;
    const int wid = tid >> 5, lane = tid & 31;
    const int wm = (wid >> 1) * 32;
    const int wn = (wid & 1) * 32;
    const int g = lane >> 2, t4 = lane & 3;
    const int ar = tid >> 1, aj = (tid & 1) * 16;
    const int bk = tid >> 3, bj = (tid & 7) * 8;

    float acc[2][4][4];
    #pragma unroll
    for (int mi = 0; mi < 2; mi++)
        #pragma unroll
        for (int ni = 0; ni < 4; ni++)
            #pragma unroll
            for (int q = 0; q < 4; q++) acc[mi][ni][q] = 0.f;

    auto load_A = [&](int buf, int k0) {
        const f16* a1 = g_Gh + (size_t)(m0+ar)*NN + k0 + aj;
        cp16(&Ash[buf][ar][aj],   a1);
        cp16(&Ash[buf][ar][aj+8], a1+8);
    };
    auto load_B = [&](int buf, int k0) {
        cp16(&Bsh[buf][bk][bj], J.X + (size_t)(k0+bk)*C + c0 + bj);
    };

    load_A(0, 0);
#if __CUDA_ARCH__ >= 900
    cudaGridDependencySynchronize();
#endif
    load_B(0, 0);
    CP_COMMIT();

    const int NIT = NN / KC;
    for (int it = 0; it < NIT; it++) {
        int buf = it & 1;
        if (it + 1 < NIT) {
            load_A(buf ^ 1, (it+1)*KC);
            load_B(buf ^ 1, (it+1)*KC);
            CP_COMMIT(); CP_WAIT(1);
        } else {
            CP_WAIT(0);
        }
        __syncthreads();

        #pragma unroll
        for (int kk = 0; kk < KC; kk += 16) {
            const int arow = lane & 15;
            const int acol = kk + ((lane >> 4) << 3);
            unsigned ah[2][4];
            #pragma unroll
            for (int mi = 0; mi < 2; mi++)
                ldsm4(ah[mi], &Ash[buf][wm + mi*16 + arow][acol]);
            const int brow = kk + (lane & 15);
            #pragma unroll
            for (int np = 0; np < 2; np++) {
                const int bcol = wn + np*16 + ((lane >> 4) << 3);
                unsigned bh[4];
                ldsm4t(bh, &Bsh[buf][brow][bcol]);
                #pragma unroll
                for (int h2 = 0; h2 < 2; h2++) {
                    int ni = np*2 + h2;
                    #pragma unroll
                    for (int mi = 0; mi < 2; mi++)
                        MMA_F16(acc[mi][ni], ah[mi], bh[h2*2], bh[h2*2+1]);
                }
            }
        }
        __syncthreads();
    }

    #pragma unroll
    for (int mi = 0; mi < 2; mi++) {
        #pragma unroll
        for (int ni = 0; ni < 4; ni++) {
            int ncol = c0 + wn + ni*8 + t4*2;
            int m1 = m0 + wm + mi*16 + g;
            store2(J.Y, (size_t)m1*C + ncol,     acc[mi][ni][0], acc[mi][ni][1]);
            store2(J.Y, (size_t)(m1+8)*C + ncol, acc[mi][ni][2], acc[mi][ni][3]);
        }
    }
}

// ---------------- gate GEMM, dual-job, fp16, K=32 per iteration ------------
struct GateArgs {
    const f16 *Ah[5];
    const f16 *Bh[5];
    int strideA, strideB, split, Fp, nt;
    const f16 *W1h; const float* b1; float* Y1;
    const f16 *W2h; const float* b2; float* Y2;
    const float* zg; float* h;
    const float* hmul; f16* t0;
    f16* e1; int e1s, e1o;
    f16* e2; int e2s, e2o;
    int fuse, t;
    const float *xin, *Wp, *bp; float* out;
    f16* dO;
    int mode;
};

__global__ __launch_bounds__(128, 4)
void gate_mma(GateArgs a0, GateArgs a1)
{
    const int tile = blockIdx.x;
    const GateArgs& a = (tile < a0.nt) ? a0 : a1;
    const int lt = (tile < a0.nt) ? tile : tile - a0.nt;
    const int zsel = lt >> 7;
    const int m0 = (lt & 127) << 6;

    const f16* Wh = (a.mode == 0 && zsel) ? a.W2h : a.W1h;
    const float* bl = (a.mode == 0 && zsel) ? a.b2 : a.b1;
    float* Yl = (a.mode == 0 && zsel) ? a.Y2 : a.Y1;

    const int tid = threadIdx.x;
    const int wid = tid >> 5, lane = tid & 31;
    const int g = lane >> 2, t4 = lane & 3;
    const int CPS = a.Fp >> 4;       // 16-chunks per slice
    const int NCH = 5 * CPS;         // total 16-chunks
    const int NIT = (NCH + 1) >> 1;  // 32-wide iterations

    __shared__ f16 Ash[2][64][GAP];
    __shared__ f16 Bsh[2][32][GBP];

    float acc[8][4];
    #pragma unroll
    for (int ni = 0; ni < 8; ni++)
        #pragma unroll
        for (int q = 0; q < 4; q++) acc[ni][q] = 0.f;

    const int arw = tid >> 1, ja = (tid & 1) * 8;
    const int bkr = tid >> 3, bjc = (tid & 7) * 8;

    // load one 16-chunk (kidx) into sub-half `sub` of buffer `buf`
    auto load_sub = [&](int buf, int kidx, int sub) {
        int s = kidx / CPS;
        int f0 = (kidx - s*CPS)*16 + ja;
        const f16* sh;
        if (f0 < a.split) sh = a.Ah[s] + (size_t)(m0+arw)*a.strideA + f0;
        else              sh = a.Bh[s] + (size_t)(m0+arw)*a.strideB + (f0 - a.split);
        cp16(&Ash[buf][arw][sub*16 + ja], sh);
        int gk = kidx*16 + bkr;
        cp16(&Bsh[buf][sub*16 + bkr][bjc], Wh + (size_t)gk*HID + bjc);
    };

    load_sub(0, 0, 0);
#if __CUDA_ARCH__ >= 900
    cudaGridDependencySynchronize();
#endif
    if (1 < NCH) load_sub(0, 1, 1);
    CP_COMMIT();

    for (int it = 0; it < NIT; it++) {
        int buf = it & 1;
        if (it + 1 < NIT) {
            int k0 = 2*(it+1);
            load_sub(buf ^ 1, k0, 0);
            if (k0 + 1 < NCH) load_sub(buf ^ 1, k0 + 1, 1);
            CP_COMMIT(); CP_WAIT(1);
        } else {
            CP_WAIT(0);
        }
        __syncthreads();

        const int arow = lane & 15;
        #pragma unroll
        for (int sub = 0; sub < 2; sub++) {
            if (2*it + sub >= NCH) break;
            const int acol = sub*16 + ((lane >> 4) << 3);
            unsigned ah[4];
            ldsm4(ah, &Ash[buf][wid*16 + arow][acol]);
            const int brow = sub*16 + (lane & 15);
            #pragma unroll
            for (int np = 0; np < 4; np++) {
                const int bcol = np*16 + ((lane >> 4) << 3);
                unsigned bh[4];
                ldsm4t(bh, &Bsh[buf][brow][bcol]);
                #pragma unroll
                for (int h2 = 0; h2 < 2; h2++) {
                    int ni = np*2 + h2;
                    MMA_F16(acc[ni], ah, bh[h2*2], bh[h2*2+1]);
                }
            }
        }
        __syncthreads();
    }

    const bool write_t0 = (a.mode == 0) && (zsel == 0) && (a.t0 != nullptr);
    float partial[2] = {0.f, 0.f};
    #pragma unroll
    for (int ni = 0; ni < 8; ni++) {
        int n = ni*8 + t4*2;
        float b0 = bl[n], b1v = bl[n+1];
        #pragma unroll
        for (int half = 0; half < 2; half++) {
            int m = m0 + wid*16 + g + half*8;
            float vx = acc[ni][half*2]   + b0;
            float vy = acc[ni][half*2+1] + b1v;
            size_t off = (size_t)m*HID + n;
            if (a.mode == 0) {
                float2 o;
                o.x = 1.f / (1.f + expf(-vx));
                o.y = 1.f / (1.f + expf(-vy));
                *reinterpret_cast<float2*>(&Yl[off]) = o;
                if (write_t0) {
                    float2 hh = *reinterpret_cast<const float2*>(&a.hmul[off]);
                    store2(a.t0, off, o.x * hh.x, o.y * hh.y);
                }
            } else {
                float2 zz = *reinterpret_cast<const float2*>(&a.zg[off]);
                float2 hh = *reinterpret_cast<float2*>(&a.h[off]);
                float2 o;
                o.x = (1.f - zz.x) * hh.x + zz.x * tanhf(vx);
                o.y = (1.f - zz.y) * hh.y + zz.y * tanhf(vy);
                *reinterpret_cast<float2*>(&a.h[off]) = o;
                if (a.e1) store2(a.e1, (size_t)m*a.e1s + a.e1o + n, o.x, o.y);
                if (a.e2) store2(a.e2, (size_t)m*a.e2s + a.e2o + n, o.x, o.y);
                if (a.fuse == 2) partial[half] += o.x * a.Wp[n] + o.y * a.Wp[n+1];
            }
        }
    }

    if (a.mode == 1 && a.fuse) {
        #pragma unroll
        for (int half = 0; half < 2; half++) {
            float p = partial[half];
            p += __shfl_xor_sync(0xffffffffu, p, 1);
            p += __shfl_xor_sync(0xffffffffu, p, 2);
            int m = m0 + wid*16 + g + half*8;
            if (t4 == 0) {
                int node = m >> 4, b = m & 15;
                if (a.fuse == 2) {
                    float s = p + a.bp[0];
                    a.out[b*(TOUT*NN) + a.t*NN + node] = s;
                    emit1(s, a.dO, (size_t)m*F0S + 64);
                } else {
                    float v = a.xin[b*(TIN*NN) + a.t*NN + node];
                    emit1(v, a.dO, (size_t)m*F0S + 64);
                }
            }
        }
    }
}

// ---------------- host driver ----------------------------------------------
extern "C" void kernel_launch(void* const* d_in, const int* in_sizes, int n_in,
                              void* d_out, int out_size)
{
    const float* x   = (const float*)d_in[0];
    const float* A   = (const float*)d_in[1];
    const float* Wr0 = (const float*)d_in[2];
    const float* br0 = (const float*)d_in[3];
    const float* Wz0 = (const float*)d_in[4];
    const float* bz0 = (const float*)d_in[5];
    const float* Wn0 = (const float*)d_in[6];
    const float* bn0 = (const float*)d_in[7];
    const float* Wr1 = (const float*)d_in[8];
    const float* br1 = (const float*)d_in[9];
    const float* Wz1 = (const float*)d_in[10];
    const float* bz1 = (const float*)d_in[11];
    const float* Wn1 = (const float*)d_in[12];
    const float* bn1 = (const float*)d_in[13];
    const float* Wp  = (const float*)d_in[14];
    const float* bp  = (const float*)d_in[15];
    float* out = (float*)d_out;

    float *G, *cs, *h0, *h1, *r0, *z0, *r1, *z1;
    f16 *Gh, *SA, *SB, *S12a, *S12b, *T0a, *T12a, *T0b, *T12b, *Wsh;
    cudaGetSymbolAddress((void**)&G,    g_G);
    cudaGetSymbolAddress((void**)&Gh,   g_Gh);
    cudaGetSymbolAddress((void**)&cs,   g_cs);
    cudaGetSymbolAddress((void**)&h0,   g_h0);
    cudaGetSymbolAddress((void**)&h1,   g_h1);
    cudaGetSymbolAddress((void**)&SA,   g_SA);
    cudaGetSymbolAddress((void**)&SB,   g_SB);
    cudaGetSymbolAddress((void**)&S12a, g_S12a);
    cudaGetSymbolAddress((void**)&S12b, g_S12b);
    cudaGetSymbolAddress((void**)&T0a,  g_T0a);
    cudaGetSymbolAddress((void**)&T12a, g_T12a);
    cudaGetSymbolAddress((void**)&T0b,  g_T0b);
    cudaGetSymbolAddress((void**)&T12b, g_T12b);
    cudaGetSymbolAddress((void**)&r0,   g_r0);
    cudaGetSymbolAddress((void**)&z0,   g_z0);
    cudaGetSymbolAddress((void**)&r1,   g_r1);
    cudaGetSymbolAddress((void**)&z1,   g_z1);
    cudaGetSymbolAddress((void**)&Wsh,  g_Wsh);

    f16 *diAll, *dih;
    cudaGetSymbolAddress((void**)&diAll, g_diAll);
    cudaGetSymbolAddress((void**)&dih,   g_dih);
    (void)diAll; (void)dih;

    rownorm_k<<<NN, 256>>>(A, G);
    colsum_k<<<2, 256>>>(A, cs);
    fill_wb_k<<<NN, 256>>>(A, cs, G);
    square_k<<<dim3(8, 8, 2), 256>>>(G, G);
    cvt_G_k<<<(4*NN*NN + 255)/256, 256>>>(G, Gh);
    int g0 = (KP0*HID + 255)/256, g1 = (KP1*HID + 255)/256;
    cvt_W0_k<<<g0, 256>>>(Wr0, Wsh + OW0R);
    cvt_W0_k<<<g0, 256>>>(Wz0, Wsh + OW0Z);
    cvt_W0_k<<<g0, 256>>>(Wn0, Wsh + OW0N);
    cvt_W1_k<<<g1, 256>>>(Wr1, Wsh + OW1R);
    cvt_W1_k<<<g1, 256>>>(Wz1, Wsh + OW1Z);
    cvt_W1_k<<<g1, 256>>>(Wn1, Wsh + OW1N);
    zero2_k<<<(NB*HID + 255)/256, 256>>>(h0, h1, NB*HID);
    zero_h_k<<<(NN*C0S + 255)/256, 256>>>(SA, NN*C0S);
    zero_h_k<<<(2*NN*C1 + 255)/256, 256>>>(SB, 2*NN*C1);

    cudaLaunchAttribute pdl_attr;
    pdl_attr.id = cudaLaunchAttributeProgrammaticStreamSerialization;
    pdl_attr.val.programmaticStreamSerializationAllowed = 1;

    auto hop2 = [&](HopJob ja, HopJob jb) {
        cudaLaunchConfig_t cfg = {};
        cfg.gridDim = dim3((unsigned)(ja.nt + jb.nt));
        cfg.blockDim = dim3(256);
        cfg.attrs = &pdl_attr; cfg.numAttrs = 1;
        cudaLaunchKernelEx(&cfg, hop4_mma, ja, jb);
    };
    auto gate2 = [&](GateArgs ga, GateArgs gb) {
        cudaLaunchConfig_t cfg = {};
        cfg.gridDim = dim3((unsigned)(ga.nt + gb.nt));
        cfg.blockDim = dim3(128);
        cfg.attrs = &pdl_attr; cfg.numAttrs = 1;
        cudaLaunchKernelEx(&cfg, gate_mma, ga, gb);
    };

    // stacked blocks 0=Wf,1=Wb,2=Wf2,3=Wb2; slice order [X,Wf,Wf2,Wb,Wb2]
    auto wire = [&](GateArgs& ga, const f16* in, const f16* s, size_t blk) {
        ga.Ah[0]=in;
        ga.Ah[1]=s;
        ga.Ah[2]=s+2*blk;
        ga.Ah[3]=s+blk;
        ga.Ah[4]=s+3*blk;
    };

    // ----- job builders -----
    auto A1 = [&](int t) -> HopJob {
        (void)t; return HopJob{SA, S12a, C0S, (C0S/64)*16};
    };
    auto A3 = [&](int t) -> HopJob {
        (void)t; return HopJob{T0a, T12a, CH, (CH/64)*16};
    };
    auto B1 = [&](int t) -> HopJob {
        size_t p = (size_t)(t & 1)*NN*C1;
        return HopJob{SB+p, S12b, C1, (C1/64)*16};
    };
    auto B3 = [&](int t) -> HopJob {
        (void)t; return HopJob{T0b, T12b, CH, (CH/64)*16};
    };
    auto A2 = [&](int t) -> GateArgs {
        (void)t;
        GateArgs ga = {};
        wire(ga, SA, S12a, (size_t)NN*C0S);
        for (int s=0;s<5;s++) ga.Bh[s]=ga.Ah[s];
        ga.strideA = F0S; ga.strideB = F0S; ga.split = F0S; ga.Fp = F0P; ga.nt = 256;
        ga.W1h = Wsh+OW0R; ga.b1 = br0; ga.Y1 = r0;
        ga.W2h = Wsh+OW0Z; ga.b2 = bz0; ga.Y2 = z0;
        ga.hmul = h0; ga.t0 = T0a;
        ga.mode = 0;
        return ga;
    };
    auto A4 = [&](int t) -> GateArgs {
        GateArgs ga = {};
        wire(ga, T0a, T12a, (size_t)NN*CH);
        size_t blk = (size_t)NN*C0S;
        ga.Bh[0]=SA+64;
        ga.Bh[1]=S12a+64;
        ga.Bh[2]=S12a+2*blk+64;
        ga.Bh[3]=S12a+blk+64;
        ga.Bh[4]=S12a+3*blk+64;
        ga.strideA = HID; ga.strideB = F0S; ga.split = HID; ga.Fp = F0P; ga.nt = 128;
        ga.W1h = Wsh+OW0N; ga.b1 = bn0;
        ga.zg = z0; ga.h = h0;
        ga.e1 = SA; ga.e1s = F0S; ga.e1o = 0;
        size_t p = (size_t)(t & 1)*NN*C1;
        ga.e2 = SB+p; ga.e2s = F1; ga.e2o = 0;
        if (t < TIN) {
            ga.fuse = 1;
            ga.t = (t + 1 < TIN) ? t + 1 : TIN - 1;
            ga.xin = x; ga.dO = SA;
        }
        ga.mode = 1;
        return ga;
    };
    auto B2 = [&](int t) -> GateArgs {
        GateArgs ga = {};
        size_t p = (size_t)(t & 1)*NN*C1;
        wire(ga, SB+p, S12b, (size_t)NN*C1);
        for (int s=0;s<5;s++) ga.Bh[s]=ga.Ah[s];
        ga.strideA = F1; ga.strideB = F1; ga.split = F1; ga.Fp = F1; ga.nt = 256;
        ga.W1h = Wsh+OW1R; ga.b1 = br1; ga.Y1 = r1;
        ga.W2h = Wsh+OW1Z; ga.b2 = bz1; ga.Y2 = z1;
        ga.hmul = h1; ga.t0 = T0b;
        ga.mode = 0;
        return ga;
    };
    auto B4 = [&](int t) -> GateArgs {
        GateArgs ga = {};
        size_t p = (size_t)(t & 1)*NN*C1;
        wire(ga, SB+p, S12b, (size_t)NN*C1);
        size_t blk = (size_t)NN*CH;
        ga.Bh[0]=T0b;
        ga.Bh[1]=T12b;
        ga.Bh[2]=T12b+2*blk;
        ga.Bh[3]=T12b+blk;
        ga.Bh[4]=T12b+3*blk;
        ga.strideA = F1; ga.strideB = HID; ga.split = HID; ga.Fp = F1; ga.nt = 128;
        ga.W1h = Wsh+OW1N; ga.b1 = bn1;
        ga.zg = z1; ga.h = h1;
        size_t pn = (size_t)((t + 1) & 1)*NN*C1;
        ga.e1 = SB+pn; ga.e1s = F1; ga.e1o = HID;
        if (t >= TIN) {
            ga.fuse = 2; ga.t = t - TIN;
            ga.Wp = Wp; ga.bp = bp; ga.out = out;
            ga.dO = SA;
        }
        ga.mode = 1;
        return ga;
    };

    auto zeroHop = [&](HopJob j) { j.nt = 0; return j; };
    auto zeroGate = [&](GateArgs g) { g.nt = 0; return g; };

    // ----- schedule -----
    copy_xt<<<NB/256, 256>>>(x, 0, SA);

    hop2(A1(0), zeroHop(A1(0)));
    gate2(A2(0), zeroGate(A2(0)));
    hop2(A3(0), zeroHop(A3(0)));
    gate2(A4(0), zeroGate(A4(0)));

    for (int j = 0; j < TIN; j++) {
        hop2(B1(j), A1(j+1));
        gate2(B2(j), A2(j+1));
        hop2(B3(j), A3(j+1));
        gate2(B4(j), A4(j+1));
    }

    hop2(B1(TIN), zeroHop(B1(TIN)));
    gate2(B2(TIN), zeroGate(B2(TIN)));
    hop2(B3(TIN), zeroHop(B3(TIN)));
    gate2(B4(TIN), zeroGate(B4(TIN)));

    for (int t = TIN + 1; t < TIN + TOUT; t++) {
        hop2(A1(t), zeroHop(A1(t)));
        gate2(A2(t), zeroGate(A2(t)));
        hop2(A3(t), zeroHop(A3(t)));
        gate2(A4(t), zeroGate(A4(t)));
        hop2(B1(t), zeroHop(B1(t)));
        gate2(B2(t), zeroGate(B2(t)));
        hop2(B3(t), zeroHop(B3(t)));
        gate2(B4(t), zeroGate(B4(t)));
    }
}